// round 6
// baseline (speedup 1.0000x reference)
#include <cuda_runtime.h>
#include <cuda_bf16.h>

#define B_  4
#define S_  512
#define D_  512
#define H_  16
#define DH_ 32
#define E_  128

// fp32 scratch (static device globals; no allocation anywhere)
__device__ float g_Q[B_*H_*S_*DH_];        // 4 MB
__device__ float g_K[B_*H_*S_*DH_];        // 4 MB
__device__ float g_V[B_*H_*S_*DH_];        // 4 MB
__device__ float g_ksum[B_*H_*S_];
__device__ float g_qsum[B_*H_*S_];
__device__ float g_RADD[B_*H_*S_*S_];      // 67 MB: folded edge term, [b,h,i,j]

// ---------------------------------------------------------------------------
// Kernel A: qkv = x @ Wqkv + bqkv  (M=2048, K=512, N=1536), scatter into
// q/k/v laid out [B,H,S,dh]. Classic 128x128x8 sgemm, 256 thr, 8x8 microtile.
// ---------------------------------------------------------------------------
__global__ void __launch_bounds__(256) qkv_gemm_kernel(
    const float* __restrict__ X, const float* __restrict__ W,
    const float* __restrict__ bias)
{
    __shared__ __align__(16) float As[8 * 132];   // A tile transposed [k][m], padded
    __shared__ __align__(16) float Bs[8 * 128];   // B tile [k][n]

    const int m0 = blockIdx.y * 128;
    const int n0 = blockIdx.x * 128;
    const int tid = threadIdx.x;
    const int tx = tid & 15;        // n-group
    const int ty = tid >> 4;        // m-group

    // loader indices
    const int lm  = tid >> 1;          // 0..127  (row of A tile)
    const int lkq = (tid & 1) * 4;     // 0 or 4  (k sub-chunk)
    const int lkr = tid >> 5;          // 0..7    (k row of B tile)
    const int lnq = (tid & 31) * 4;    // 0..124  (n sub-chunk)

    const float* Ag = X + (size_t)(m0 + lm) * 512 + lkq;
    const float* Bg = W + (size_t)lkr * 1536 + n0 + lnq;

    float acc[8][8];
#pragma unroll
    for (int i = 0; i < 8; i++)
#pragma unroll
        for (int j = 0; j < 8; j++) acc[i][j] = 0.0f;

    for (int k0 = 0; k0 < 512; k0 += 8) {
        __syncthreads();
        float4 av = *(const float4*)(Ag + k0);
        float4 bv = *(const float4*)(Bg + (size_t)k0 * 1536);
        As[(lkq + 0) * 132 + lm] = av.x;
        As[(lkq + 1) * 132 + lm] = av.y;
        As[(lkq + 2) * 132 + lm] = av.z;
        As[(lkq + 3) * 132 + lm] = av.w;
        *(float4*)(Bs + lkr * 128 + lnq) = bv;
        __syncthreads();

#pragma unroll
        for (int kk = 0; kk < 8; kk++) {
            float a[8], b[8];
            *(float4*)(a)     = *(const float4*)(As + kk * 132 + ty * 8);
            *(float4*)(a + 4) = *(const float4*)(As + kk * 132 + ty * 8 + 4);
            *(float4*)(b)     = *(const float4*)(Bs + kk * 128 + tx * 8);
            *(float4*)(b + 4) = *(const float4*)(Bs + kk * 128 + tx * 8 + 4);
#pragma unroll
            for (int i = 0; i < 8; i++)
#pragma unroll
                for (int j = 0; j < 8; j++)
                    acc[i][j] += a[i] * b[j];
        }
    }

    // epilogue: scatter into q/k/v [B,H,S,dh]
#pragma unroll
    for (int i = 0; i < 8; i++) {
        const int m = m0 + ty * 8 + i;
        const int bb = m >> 9;          // /512
        const int s  = m & 511;
#pragma unroll
        for (int j = 0; j < 8; j++) {
            const int n = n0 + tx * 8 + j;
            const int h  = n / 96;
            const int r  = n - h * 96;
            const int t3 = r >> 5;      // 0=q,1=k,2=v
            const int d  = r & 31;
            const float v = acc[i][j] + bias[n];
            float* dst = (t3 == 0) ? g_Q : ((t3 == 1) ? g_K : g_V);
            dst[((size_t)(bb * H_ + h) * S_ + s) * DH_ + d] = v;
        }
    }
}

// ---------------------------------------------------------------------------
// Kernel A2: qsum/ksum over dh (indexed by the SAME position as the query).
// ---------------------------------------------------------------------------
__global__ void __launch_bounds__(256) sums_kernel()
{
    const int r = blockIdx.x * 256 + threadIdx.x;   // 0 .. B*H*S-1 (32768)
    const float4* q4 = (const float4*)(g_Q + (size_t)r * DH_);
    const float4* k4 = (const float4*)(g_K + (size_t)r * DH_);
    float sq = 0.0f, sk = 0.0f;
#pragma unroll
    for (int u = 0; u < 8; u++) {
        float4 a = q4[u]; sq += (a.x + a.y) + (a.z + a.w);
        float4 c = k4[u]; sk += (c.x + c.y) + (c.z + c.w);
    }
    g_qsum[r] = sq;
    g_ksum[r] = sk;
}

// ---------------------------------------------------------------------------
// Kernel B: folded edge projection.
// RADD[b,h,i,j] = sum_e p[b,i,j,e] * (Wrqk[e,2h]*ksum[b,h,i] + Wrqk[e,2h+1]*qsum[b,h,i])
//              + brqk[2h]*ksum + brqk[2h+1]*qsum
// One CTA = (b, i, 64-j tile). p staged transposed in smem (conflict-free).
// 128 threads: warp = 4-head group, lane = j residue (strided j ownership).
// ---------------------------------------------------------------------------
__global__ void __launch_bounds__(128) radd_kernel(
    const float* __restrict__ P, const float* __restrict__ Wrqk,
    const float* __restrict__ brqk)
{
    __shared__ __align__(16) float pT[128 * 65];   // [e][j], stride 65 -> conflict-free
    __shared__ __align__(16) float Wc[128 * 16];   // folded weights [e][h]
    __shared__ float kss[16], qss[16], badd[16];

    const int b  = blockIdx.z;
    const int i  = blockIdx.y;
    const int j0 = blockIdx.x * 64;
    const int tid = threadIdx.x;

    if (tid < 16) {
        kss[tid] = g_ksum[(size_t)(b * H_ + tid) * S_ + i];
        qss[tid] = g_qsum[(size_t)(b * H_ + tid) * S_ + i];
    }
    __syncthreads();

    // build folded weights + folded bias
    for (int f = tid; f < 128 * 16; f += 128) {
        const int e = f >> 4;
        const int h = f & 15;
        Wc[f] = Wrqk[e * 32 + 2 * h] * kss[h] + Wrqk[e * 32 + 2 * h + 1] * qss[h];
    }
    if (tid < 16)
        badd[tid] = brqk[2 * tid] * kss[tid] + brqk[2 * tid + 1] * qss[tid];

    // stage p tile transposed: lanes sweep e (coalesced gmem, conflict-free STS)
    const float* pg = P + ((size_t)(b * S_ + i) * S_ + j0) * E_;
    for (int f = tid; f < 64 * 128; f += 128) {
        const int e = f & 127;
        const int j = f >> 7;
        pT[e * 65 + j] = pg[(size_t)j * 128 + e];
    }
    __syncthreads();

    const int jg = tid & 31;     // lane -> j residue
    const int hg = tid >> 5;     // warp -> head group (4 heads)
    const float4* Wc4 = (const float4*)Wc;

    float acc[2][4];
#pragma unroll
    for (int a = 0; a < 2; a++)
#pragma unroll
        for (int c = 0; c < 4; c++) acc[a][c] = 0.0f;

#pragma unroll 4
    for (int e = 0; e < 128; e++) {
        const float4 w = Wc4[e * 4 + hg];               // warp-uniform broadcast
        const float p0 = pT[e * 65 + jg];               // conflict-free
        const float p1 = pT[e * 65 + 32 + jg];
        acc[0][0] += p0 * w.x; acc[0][1] += p0 * w.y;
        acc[0][2] += p0 * w.z; acc[0][3] += p0 * w.w;
        acc[1][0] += p1 * w.x; acc[1][1] += p1 * w.y;
        acc[1][2] += p1 * w.z; acc[1][3] += p1 * w.w;
    }

#pragma unroll
    for (int hh = 0; hh < 4; hh++) {
        const int h = hg * 4 + hh;
        const float ba = badd[h];
        const size_t base = ((size_t)(b * H_ + h) * S_ + i) * S_ + j0;
        g_RADD[base + jg]      = acc[0][hh] + ba;       // coalesced
        g_RADD[base + 32 + jg] = acc[1][hh] + ba;
    }
}

// ---------------------------------------------------------------------------
// Kernel C: fused attention per (b, h, 64-query tile), streaming online
// softmax over 64-key tiles. scores = q.k + RADD, mask -> -10000, *scale.
// ---------------------------------------------------------------------------
__global__ void __launch_bounds__(256) attn_kernel(
    const int* __restrict__ mask, float* __restrict__ out)
{
    __shared__ __align__(16) float q_s[32 * 68];   // [d][i] padded
    __shared__ __align__(16) float k_s[32 * 68];   // [d][j] padded
    __shared__ __align__(16) float v_s[64 * 32];   // [j][d]
    __shared__ __align__(16) float s_s[64 * 68];   // [i][j] padded (scores/probs)

    const int b  = blockIdx.z;
    const int h  = blockIdx.y;
    const int i0 = blockIdx.x * 64;
    const int tid  = threadIdx.x;
    const int lane = tid & 31;
    const int w    = tid >> 5;            // warp id: owns rows w*8..w*8+7
    const int tx = tid & 15;              // QK j-group
    const int ty = tid >> 4;              // QK i-group

    const float scale   = 0.10206207261596576f;   // 1/sqrt(96)
    const float maskval = -10000.0f * 0.10206207261596576f;

    // load q tile transposed
    {
        const float* qg = g_Q + ((size_t)(b * H_ + h) * S_ + i0) * DH_;
        for (int f = tid; f < 64 * 32; f += 256) {
            const int i = f >> 5;
            const int d = f & 31;
            q_s[d * 68 + i] = qg[f];
        }
    }

    float m_run[8], l_run[8], oacc[8];
#pragma unroll
    for (int rr = 0; rr < 8; rr++) { m_run[rr] = -1e30f; l_run[rr] = 0.0f; oacc[rr] = 0.0f; }

    for (int j0 = 0; j0 < S_; j0 += 64) {
        __syncthreads();   // q ready (iter 0); prev PV done with s_s/v_s

        // stage k (transposed) and v tiles
        const float* kg = g_K + ((size_t)(b * H_ + h) * S_ + j0) * DH_;
        const float* vg = g_V + ((size_t)(b * H_ + h) * S_ + j0) * DH_;
        for (int f = tid; f < 64 * 32; f += 256) {
            const int j = f >> 5;
            const int d = f & 31;
            k_s[d * 68 + j] = kg[f];
            v_s[f] = vg[f];
        }
        __syncthreads();

        // --- QK^T 64x64 tile, 4x4 microtile per thread ---
        float acc[4][4];
#pragma unroll
        for (int a = 0; a < 4; a++)
#pragma unroll
            for (int c = 0; c < 4; c++) acc[a][c] = 0.0f;

#pragma unroll
        for (int d = 0; d < 32; d++) {
            float4 a4 = *(const float4*)(q_s + d * 68 + ty * 4);
            float4 b4 = *(const float4*)(k_s + d * 68 + tx * 4);
            float av[4] = {a4.x, a4.y, a4.z, a4.w};
            float bv[4] = {b4.x, b4.y, b4.z, b4.w};
#pragma unroll
            for (int ii = 0; ii < 4; ii++)
#pragma unroll
                for (int jj = 0; jj < 4; jj++)
                    acc[ii][jj] += av[ii] * bv[jj];
        }

        // + RADD, mask, scale -> s_s
#pragma unroll
        for (int ii = 0; ii < 4; ii++) {
            const int i = i0 + ty * 4 + ii;
            const float4 r4 = *(const float4*)(g_RADD +
                ((size_t)(b * H_ + h) * S_ + i) * S_ + j0 + tx * 4);
            const int4 mk = *(const int4*)(mask +
                ((size_t)(b * S_ + i)) * S_ + j0 + tx * 4);
            float4 sv;
            sv.x = (mk.x != 0) ? (acc[ii][0] + r4.x) * scale : maskval;
            sv.y = (mk.y != 0) ? (acc[ii][1] + r4.y) * scale : maskval;
            sv.z = (mk.z != 0) ? (acc[ii][2] + r4.z) * scale : maskval;
            sv.w = (mk.w != 0) ? (acc[ii][3] + r4.w) * scale : maskval;
            *(float4*)(s_s + (ty * 4 + ii) * 68 + tx * 4) = sv;
        }
        __syncthreads();

        // --- online softmax: warp w owns rows w*8..w*8+7 ---
#pragma unroll
        for (int rr = 0; rr < 8; rr++) {
            const int r = w * 8 + rr;
            const float x0 = s_s[r * 68 + lane];
            const float x1 = s_s[r * 68 + 32 + lane];
            float mx = fmaxf(x0, x1);
#pragma unroll
            for (int off = 16; off > 0; off >>= 1)
                mx = fmaxf(mx, __shfl_xor_sync(0xffffffffu, mx, off));
            const float m_new = fmaxf(m_run[rr], mx);
            const float e0 = __expf(x0 - m_new);
            const float e1 = __expf(x1 - m_new);
            s_s[r * 68 + lane]      = e0;
            s_s[r * 68 + 32 + lane] = e1;
            float sm = e0 + e1;
#pragma unroll
            for (int off = 16; off > 0; off >>= 1)
                sm += __shfl_xor_sync(0xffffffffu, sm, off);
            const float alpha = __expf(m_run[rr] - m_new);
            l_run[rr] = l_run[rr] * alpha + sm;
            m_run[rr] = m_new;
            oacc[rr] *= alpha;
        }
        __syncwarp();

        // --- PV accumulate: lane = d, warp rows w*8..+7 ---
#pragma unroll 4
        for (int j4 = 0; j4 < 64; j4 += 4) {
            const float v0 = v_s[(j4 + 0) * 32 + lane];
            const float v1 = v_s[(j4 + 1) * 32 + lane];
            const float v2 = v_s[(j4 + 2) * 32 + lane];
            const float v3 = v_s[(j4 + 3) * 32 + lane];
#pragma unroll
            for (int rr = 0; rr < 8; rr++) {
                const float4 pv = *(const float4*)(s_s + (w * 8 + rr) * 68 + j4);
                oacc[rr] += pv.x * v0 + pv.y * v1 + pv.z * v2 + pv.w * v3;
            }
        }
    }

    // write output [B,S,D] with D index = h*32 + d
#pragma unroll
    for (int rr = 0; rr < 8; rr++) {
        const int i = i0 + w * 8 + rr;
        out[((size_t)(b * S_ + i)) * D_ + h * DH_ + lane] = oacc[rr] / l_run[rr];
    }
}

// ---------------------------------------------------------------------------
extern "C" void kernel_launch(void* const* d_in, const int* in_sizes, int n_in,
                              void* d_out, int out_size)
{
    const float* x     = (const float*)d_in[0];
    const float* p     = (const float*)d_in[1];
    const int*   mask  = (const int*)  d_in[2];
    const float* Wqkv  = (const float*)d_in[3];
    const float* bqkv  = (const float*)d_in[4];
    const float* Wrqk  = (const float*)d_in[5];
    const float* brqk  = (const float*)d_in[6];
    float* out = (float*)d_out;

    (void)in_sizes; (void)n_in; (void)out_size;

    qkv_gemm_kernel<<<dim3(1536 / 128, 2048 / 128), 256>>>(x, Wqkv, bqkv);
    sums_kernel<<<(B_ * H_ * S_) / 256, 256>>>();
    radd_kernel<<<dim3(S_ / 64, S_, B_), 128>>>(p, Wrqk, brqk);
    attn_kernel<<<dim3(S_ / 64, H_, B_), 256>>>(mask, out);
}

// round 7
// speedup vs baseline: 1.0165x; 1.0165x over previous
#include <cuda_runtime.h>
#include <cuda_bf16.h>

#define B_  4
#define S_  512
#define D_  512
#define H_  16
#define DH_ 32
#define E_  128

typedef unsigned long long ull;

// ---- f32x2 packed-math helpers (sm_103a FFMA2 path, PTX-only) -------------
__device__ __forceinline__ ull pack2(float x, float y) {
    ull r; asm("mov.b64 %0, {%1, %2};" : "=l"(r) : "f"(x), "f"(y)); return r;
}
__device__ __forceinline__ void ffma2(ull& d, ull a, ull b) {
    asm("fma.rn.f32x2 %0, %1, %2, %0;" : "+l"(d) : "l"(a), "l"(b));
}
__device__ __forceinline__ ull fmul2(ull a, ull b) {
    ull r; asm("mul.rn.f32x2 %0, %1, %2;" : "=l"(r) : "l"(a), "l"(b)); return r;
}
__device__ __forceinline__ float2 unpack2(ull v) {
    float2 f; asm("mov.b64 {%0, %1}, %2;" : "=f"(f.x), "=f"(f.y) : "l"(v)); return f;
}

// fp32 scratch (static device globals; no allocation anywhere)
__device__ float g_Q[B_*H_*S_*DH_];
__device__ float g_K[B_*H_*S_*DH_];
__device__ float g_V[B_*H_*S_*DH_];
__device__ float g_ksum[B_*H_*S_];
__device__ float g_qsum[B_*H_*S_];
__device__ float g_RADD[B_*H_*S_*S_];      // folded edge term, [b,h,i,j]

// ---------------------------------------------------------------------------
// Kernel A: qkv = x @ Wqkv + bqkv  (M=2048, K=512, N=1536). Double-buffered
// 128x128x8 sgemm, FFMA2 inner product (acc pairs over n).
// ---------------------------------------------------------------------------
__global__ void __launch_bounds__(256) qkv_gemm_kernel(
    const float* __restrict__ X, const float* __restrict__ W,
    const float* __restrict__ bias)
{
    __shared__ __align__(16) float As[2][8 * 132];
    __shared__ __align__(16) float Bs[2][8 * 128];

    const int m0 = blockIdx.y * 128;
    const int n0 = blockIdx.x * 128;
    const int tid = threadIdx.x;
    const int tx = tid & 15;
    const int ty = tid >> 4;

    const int lm  = tid >> 1;
    const int lkq = (tid & 1) * 4;
    const int lkr = tid >> 5;
    const int lnq = (tid & 31) * 4;

    const float* Ag = X + (size_t)(m0 + lm) * 512 + lkq;
    const float* Bg = W + (size_t)lkr * 1536 + n0 + lnq;

    ull acc2[8][4];
#pragma unroll
    for (int i = 0; i < 8; i++)
#pragma unroll
        for (int j = 0; j < 4; j++) acc2[i][j] = 0ULL;

    // preload tile 0
    {
        float4 av = *(const float4*)(Ag);
        float4 bv = *(const float4*)(Bg);
        As[0][(lkq + 0) * 132 + lm] = av.x;
        As[0][(lkq + 1) * 132 + lm] = av.y;
        As[0][(lkq + 2) * 132 + lm] = av.z;
        As[0][(lkq + 3) * 132 + lm] = av.w;
        *(float4*)(&Bs[0][lkr * 128 + lnq]) = bv;
    }
    __syncthreads();

    int buf = 0;
    for (int k0 = 0; k0 < 512; k0 += 8) {
        const bool has_next = (k0 + 8) < 512;
        float4 av, bv;
        if (has_next) {
            av = *(const float4*)(Ag + k0 + 8);
            bv = *(const float4*)(Bg + (size_t)(k0 + 8) * 1536);
        }

        const float* Asb = As[buf];
        const float* Bsb = Bs[buf];
#pragma unroll
        for (int kk = 0; kk < 8; kk++) {
            float a[8];
            *(float4*)(a)     = *(const float4*)(Asb + kk * 132 + ty * 8);
            *(float4*)(a + 4) = *(const float4*)(Asb + kk * 132 + ty * 8 + 4);
            ulonglong2 b01 = *(const ulonglong2*)(Bsb + kk * 128 + tx * 8);
            ulonglong2 b23 = *(const ulonglong2*)(Bsb + kk * 128 + tx * 8 + 4);
            ull bp0 = b01.x, bp1 = b01.y, bp2 = b23.x, bp3 = b23.y;
#pragma unroll
            for (int i = 0; i < 8; i++) {
                const ull ap = pack2(a[i], a[i]);
                ffma2(acc2[i][0], ap, bp0);
                ffma2(acc2[i][1], ap, bp1);
                ffma2(acc2[i][2], ap, bp2);
                ffma2(acc2[i][3], ap, bp3);
            }
        }

        if (has_next) {
            const int nb = buf ^ 1;
            As[nb][(lkq + 0) * 132 + lm] = av.x;
            As[nb][(lkq + 1) * 132 + lm] = av.y;
            As[nb][(lkq + 2) * 132 + lm] = av.z;
            As[nb][(lkq + 3) * 132 + lm] = av.w;
            *(float4*)(&Bs[nb][lkr * 128 + lnq]) = bv;
            __syncthreads();
            buf = nb;
        }
    }

    // epilogue: scatter into q/k/v [B,H,S,dh]
#pragma unroll
    for (int i = 0; i < 8; i++) {
        const int m = m0 + ty * 8 + i;
        const int bb = m >> 9;
        const int s  = m & 511;
#pragma unroll
        for (int jp = 0; jp < 4; jp++) {
            const float2 vv = unpack2(acc2[i][jp]);
            const float vs[2] = {vv.x, vv.y};
#pragma unroll
            for (int q = 0; q < 2; q++) {
                const int n = n0 + tx * 8 + jp * 2 + q;
                const int h  = n / 96;
                const int r  = n - h * 96;
                const int t3 = r >> 5;
                const int d  = r & 31;
                const float v = vs[q] + bias[n];
                float* dst = (t3 == 0) ? g_Q : ((t3 == 1) ? g_K : g_V);
                dst[((size_t)(bb * H_ + h) * S_ + s) * DH_ + d] = v;
            }
        }
    }
}

// ---------------------------------------------------------------------------
// Kernel A2: qsum/ksum over dh.
// ---------------------------------------------------------------------------
__global__ void __launch_bounds__(256) sums_kernel()
{
    const int r = blockIdx.x * 256 + threadIdx.x;
    const float4* q4 = (const float4*)(g_Q + (size_t)r * DH_);
    const float4* k4 = (const float4*)(g_K + (size_t)r * DH_);
    float sq = 0.0f, sk = 0.0f;
#pragma unroll
    for (int u = 0; u < 8; u++) {
        float4 a = q4[u]; sq += (a.x + a.y) + (a.z + a.w);
        float4 c = k4[u]; sk += (c.x + c.y) + (c.z + c.w);
    }
    g_qsum[r] = sq;
    g_ksum[r] = sk;
}

// ---------------------------------------------------------------------------
// Kernel B: folded edge projection.
// RADD[b,h,i,j] = sum_e p[b,i,j,e]*Wc[e,h] + badd[h],
//   Wc[e,h] = Wrqk[e,2h]*ksum[b,h,i] + Wrqk[e,2h+1]*qsum[b,h,i]
// CTA = (b, i, 64-j tile), 128 threads. Thread = 1 j x 8 heads (FFMA2 pairs).
// Warp layout: hg constant per warp -> Wc reads are free broadcasts.
// ---------------------------------------------------------------------------
__global__ void __launch_bounds__(128) radd_kernel(
    const float* __restrict__ P, const float* __restrict__ Wrqk,
    const float* __restrict__ brqk)
{
    __shared__ __align__(16) float pT[128 * 65];   // [e][j], conflict-free
    __shared__ __align__(16) float Wc[128 * 16];   // folded weights [e][h]
    __shared__ float kss[16], qss[16], badd[16];

    const int b  = blockIdx.z;
    const int i  = blockIdx.y;
    const int j0 = blockIdx.x * 64;
    const int tid = threadIdx.x;

    if (tid < 16) {
        kss[tid] = g_ksum[(size_t)(b * H_ + tid) * S_ + i];
        qss[tid] = g_qsum[(size_t)(b * H_ + tid) * S_ + i];
    }
    __syncthreads();

    for (int f = tid; f < 128 * 16; f += 128) {
        const int e = f >> 4;
        const int h = f & 15;
        Wc[f] = Wrqk[e * 32 + 2 * h] * kss[h] + Wrqk[e * 32 + 2 * h + 1] * qss[h];
    }
    if (tid < 16)
        badd[tid] = brqk[2 * tid] * kss[tid] + brqk[2 * tid + 1] * qss[tid];

    // stage p tile transposed (coalesced LDG over e, conflict-free STS)
    const float* pg = P + ((size_t)(b * S_ + i) * S_ + j0) * E_;
    for (int f = tid; f < 64 * 128; f += 128) {
        const int e = f & 127;
        const int j = f >> 7;
        pT[e * 65 + j] = pg[(size_t)j * 128 + e];
    }
    __syncthreads();

    const int jg = tid & 63;     // 0..63 j within tile (warp-contiguous)
    const int hg = tid >> 6;     // 0/1 -> heads hg*8 .. hg*8+7

    ull acc2[4];
#pragma unroll
    for (int k = 0; k < 4; k++) acc2[k] = 0ULL;

#pragma unroll 4
    for (int e = 0; e < 128; e++) {
        const float pv = pT[e * 65 + jg];
        const ull pp = pack2(pv, pv);
        const ulonglong2 w01 = *(const ulonglong2*)(Wc + e * 16 + hg * 8);
        const ulonglong2 w23 = *(const ulonglong2*)(Wc + e * 16 + hg * 8 + 4);
        ffma2(acc2[0], pp, w01.x);
        ffma2(acc2[1], pp, w01.y);
        ffma2(acc2[2], pp, w23.x);
        ffma2(acc2[3], pp, w23.y);
    }

#pragma unroll
    for (int k = 0; k < 4; k++) {
        const float2 v = unpack2(acc2[k]);
        const int h0 = hg * 8 + 2 * k;
        const int h1 = h0 + 1;
        g_RADD[((size_t)(b * H_ + h0) * S_ + i) * S_ + j0 + jg] = v.x + badd[h0];
        g_RADD[((size_t)(b * H_ + h1) * S_ + i) * S_ + j0 + jg] = v.y + badd[h1];
    }
}

// ---------------------------------------------------------------------------
// Kernel C: fused attention per (b, h, 64-query tile). FFMA2 in QK and PV.
// ---------------------------------------------------------------------------
__global__ void __launch_bounds__(256) attn_kernel(
    const int* __restrict__ mask, float* __restrict__ out)
{
    __shared__ __align__(16) float q_s[32 * 68];   // [d][i]
    __shared__ __align__(16) float k_s[32 * 68];   // [d][j]
    __shared__ __align__(16) float v_s[64 * 32];   // [j][d]
    __shared__ __align__(16) float s_s[64 * 68];   // [i][j]

    const int b  = blockIdx.z;
    const int h  = blockIdx.y;
    const int i0 = blockIdx.x * 64;
    const int tid  = threadIdx.x;
    const int lane = tid & 31;
    const int w    = tid >> 5;
    const int tx = tid & 15;
    const int ty = tid >> 4;

    const float scale   = 0.10206207261596576f;   // 1/sqrt(96)
    const float maskval = -10000.0f * 0.10206207261596576f;

    {
        const float* qg = g_Q + ((size_t)(b * H_ + h) * S_ + i0) * DH_;
        for (int f = tid; f < 64 * 32; f += 256) {
            const int i = f >> 5;
            const int d = f & 31;
            q_s[d * 68 + i] = qg[f];
        }
    }

    float m_run[8], l_run[8];
    ull oacc2[8];
#pragma unroll
    for (int rr = 0; rr < 8; rr++) { m_run[rr] = -1e30f; l_run[rr] = 0.0f; oacc2[rr] = 0ULL; }

    for (int j0 = 0; j0 < S_; j0 += 64) {
        __syncthreads();

        const float* kg = g_K + ((size_t)(b * H_ + h) * S_ + j0) * DH_;
        const float* vg = g_V + ((size_t)(b * H_ + h) * S_ + j0) * DH_;
        for (int f = tid; f < 64 * 32; f += 256) {
            const int j = f >> 5;
            const int d = f & 31;
            k_s[d * 68 + j] = kg[f];
            v_s[f] = vg[f];
        }
        __syncthreads();

        // --- QK^T 64x64 tile, FFMA2 pairs over j ---
        ull acc2[4][2];
#pragma unroll
        for (int a = 0; a < 4; a++) { acc2[a][0] = 0ULL; acc2[a][1] = 0ULL; }

#pragma unroll
        for (int d = 0; d < 32; d++) {
            float av[4];
            *(float4*)(av) = *(const float4*)(q_s + d * 68 + ty * 4);
            const ulonglong2 bq = *(const ulonglong2*)(k_s + d * 68 + tx * 4);
#pragma unroll
            for (int ii = 0; ii < 4; ii++) {
                const ull ap = pack2(av[ii], av[ii]);
                ffma2(acc2[ii][0], ap, bq.x);
                ffma2(acc2[ii][1], ap, bq.y);
            }
        }

        // + RADD, mask, scale -> s_s
#pragma unroll
        for (int ii = 0; ii < 4; ii++) {
            const int i = i0 + ty * 4 + ii;
            const float4 r4 = *(const float4*)(g_RADD +
                ((size_t)(b * H_ + h) * S_ + i) * S_ + j0 + tx * 4);
            const int4 mk = *(const int4*)(mask +
                ((size_t)(b * S_ + i)) * S_ + j0 + tx * 4);
            const float2 p01 = unpack2(acc2[ii][0]);
            const float2 p23 = unpack2(acc2[ii][1]);
            float4 sv;
            sv.x = (mk.x != 0) ? (p01.x + r4.x) * scale : maskval;
            sv.y = (mk.y != 0) ? (p01.y + r4.y) * scale : maskval;
            sv.z = (mk.z != 0) ? (p23.x + r4.z) * scale : maskval;
            sv.w = (mk.w != 0) ? (p23.y + r4.w) * scale : maskval;
            *(float4*)(s_s + (ty * 4 + ii) * 68 + tx * 4) = sv;
        }
        __syncthreads();

        // --- online softmax: warp w owns rows w*8..w*8+7 ---
#pragma unroll
        for (int rr = 0; rr < 8; rr++) {
            const int r = w * 8 + rr;
            const float x0 = s_s[r * 68 + lane];
            const float x1 = s_s[r * 68 + 32 + lane];
            float mx = fmaxf(x0, x1);
#pragma unroll
            for (int off = 16; off > 0; off >>= 1)
                mx = fmaxf(mx, __shfl_xor_sync(0xffffffffu, mx, off));
            const float m_new = fmaxf(m_run[rr], mx);
            const float e0 = __expf(x0 - m_new);
            const float e1 = __expf(x1 - m_new);
            s_s[r * 68 + lane]      = e0;
            s_s[r * 68 + 32 + lane] = e1;
            float sm = e0 + e1;
#pragma unroll
            for (int off = 16; off > 0; off >>= 1)
                sm += __shfl_xor_sync(0xffffffffu, sm, off);
            const float alpha = __expf(m_run[rr] - m_new);
            l_run[rr] = l_run[rr] * alpha + sm;
            m_run[rr] = m_new;
            oacc2[rr] = fmul2(oacc2[rr], pack2(alpha, alpha));
        }
        __syncwarp();

        // --- PV accumulate with FFMA2 (pairs over j) ---
#pragma unroll 4
        for (int j4 = 0; j4 < 64; j4 += 4) {
            const float v0 = v_s[(j4 + 0) * 32 + lane];
            const float v1 = v_s[(j4 + 1) * 32 + lane];
            const float v2 = v_s[(j4 + 2) * 32 + lane];
            const float v3 = v_s[(j4 + 3) * 32 + lane];
            const ull vp01 = pack2(v0, v1);
            const ull vp23 = pack2(v2, v3);
#pragma unroll
            for (int rr = 0; rr < 8; rr++) {
                const ulonglong2 pp = *(const ulonglong2*)(s_s + (w * 8 + rr) * 68 + j4);
                ffma2(oacc2[rr], pp.x, vp01);
                ffma2(oacc2[rr], pp.y, vp23);
            }
        }
    }

#pragma unroll
    for (int rr = 0; rr < 8; rr++) {
        const int i = i0 + w * 8 + rr;
        const float2 o = unpack2(oacc2[rr]);
        out[((size_t)(b * S_ + i)) * D_ + h * DH_ + lane] = (o.x + o.y) / l_run[rr];
    }
}

// ---------------------------------------------------------------------------
extern "C" void kernel_launch(void* const* d_in, const int* in_sizes, int n_in,
                              void* d_out, int out_size)
{
    const float* x     = (const float*)d_in[0];
    const float* p     = (const float*)d_in[1];
    const int*   mask  = (const int*)  d_in[2];
    const float* Wqkv  = (const float*)d_in[3];
    const float* bqkv  = (const float*)d_in[4];
    const float* Wrqk  = (const float*)d_in[5];
    const float* brqk  = (const float*)d_in[6];
    float* out = (float*)d_out;

    (void)in_sizes; (void)n_in; (void)out_size;

    qkv_gemm_kernel<<<dim3(1536 / 128, 2048 / 128), 256>>>(x, Wqkv, bqkv);
    sums_kernel<<<(B_ * H_ * S_) / 256, 256>>>();
    radd_kernel<<<dim3(S_ / 64, S_, B_), 128>>>(p, Wrqk, brqk);
    attn_kernel<<<dim3(S_ / 64, H_, B_), 256>>>(mask, out);
}

// round 8
// speedup vs baseline: 1.2093x; 1.1897x over previous
#include <cuda_runtime.h>
#include <cuda_bf16.h>

#define B_  4
#define S_  512
#define D_  512
#define H_  16
#define DH_ 32
#define E_  128

typedef unsigned long long ull;

// ---- f32x2 packed-math helpers (sm_103a FFMA2 path, PTX-only) -------------
__device__ __forceinline__ ull pack2(float x, float y) {
    ull r; asm("mov.b64 %0, {%1, %2};" : "=l"(r) : "f"(x), "f"(y)); return r;
}
__device__ __forceinline__ void ffma2(ull& d, ull a, ull b) {
    asm("fma.rn.f32x2 %0, %1, %2, %0;" : "+l"(d) : "l"(a), "l"(b));
}
__device__ __forceinline__ ull fmul2(ull a, ull b) {
    ull r; asm("mul.rn.f32x2 %0, %1, %2;" : "=l"(r) : "l"(a), "l"(b)); return r;
}
__device__ __forceinline__ float2 unpack2(ull v) {
    float2 f; asm("mov.b64 {%0, %1}, %2;" : "=f"(f.x), "=f"(f.y) : "l"(v)); return f;
}

// scale * log2(e): scores are pre-multiplied so softmax uses exp2f directly.
#define SCALE_L2E (0.10206207261596576f * 1.4426950408889634f)

// fp32 scratch (static device globals; no allocation anywhere)
__device__ float g_Q[B_*H_*S_*DH_];
__device__ float g_K[B_*H_*S_*DH_];
__device__ float g_V[B_*H_*S_*DH_];
__device__ float g_ksum[B_*H_*S_];
__device__ float g_qsum[B_*H_*S_];
__device__ float g_RADD[B_*H_*S_*S_];      // folded edge term * SCALE_L2E, [b,h,i,j]

// ---------------------------------------------------------------------------
// Kernel A: qkv = x @ Wqkv + bqkv  (M=2048, K=512, N=1536). Double-buffered
// 128x128x8 sgemm, FFMA2 inner product.
// ---------------------------------------------------------------------------
__global__ void __launch_bounds__(256) qkv_gemm_kernel(
    const float* __restrict__ X, const float* __restrict__ W,
    const float* __restrict__ bias)
{
    __shared__ __align__(16) float As[2][8 * 132];
    __shared__ __align__(16) float Bs[2][8 * 128];

    const int m0 = blockIdx.y * 128;
    const int n0 = blockIdx.x * 128;
    const int tid = threadIdx.x;
    const int tx = tid & 15;
    const int ty = tid >> 4;

    const int lm  = tid >> 1;
    const int lkq = (tid & 1) * 4;
    const int lkr = tid >> 5;
    const int lnq = (tid & 31) * 4;

    const float* Ag = X + (size_t)(m0 + lm) * 512 + lkq;
    const float* Bg = W + (size_t)lkr * 1536 + n0 + lnq;

    ull acc2[8][4];
#pragma unroll
    for (int i = 0; i < 8; i++)
#pragma unroll
        for (int j = 0; j < 4; j++) acc2[i][j] = 0ULL;

    {
        float4 av = *(const float4*)(Ag);
        float4 bv = *(const float4*)(Bg);
        As[0][(lkq + 0) * 132 + lm] = av.x;
        As[0][(lkq + 1) * 132 + lm] = av.y;
        As[0][(lkq + 2) * 132 + lm] = av.z;
        As[0][(lkq + 3) * 132 + lm] = av.w;
        *(float4*)(&Bs[0][lkr * 128 + lnq]) = bv;
    }
    __syncthreads();

    int buf = 0;
    for (int k0 = 0; k0 < 512; k0 += 8) {
        const bool has_next = (k0 + 8) < 512;
        float4 av, bv;
        if (has_next) {
            av = *(const float4*)(Ag + k0 + 8);
            bv = *(const float4*)(Bg + (size_t)(k0 + 8) * 1536);
        }

        const float* Asb = As[buf];
        const float* Bsb = Bs[buf];
#pragma unroll
        for (int kk = 0; kk < 8; kk++) {
            float a[8];
            *(float4*)(a)     = *(const float4*)(Asb + kk * 132 + ty * 8);
            *(float4*)(a + 4) = *(const float4*)(Asb + kk * 132 + ty * 8 + 4);
            ulonglong2 b01 = *(const ulonglong2*)(Bsb + kk * 128 + tx * 8);
            ulonglong2 b23 = *(const ulonglong2*)(Bsb + kk * 128 + tx * 8 + 4);
            ull bp0 = b01.x, bp1 = b01.y, bp2 = b23.x, bp3 = b23.y;
#pragma unroll
            for (int i = 0; i < 8; i++) {
                const ull ap = pack2(a[i], a[i]);
                ffma2(acc2[i][0], ap, bp0);
                ffma2(acc2[i][1], ap, bp1);
                ffma2(acc2[i][2], ap, bp2);
                ffma2(acc2[i][3], ap, bp3);
            }
        }

        if (has_next) {
            const int nb = buf ^ 1;
            As[nb][(lkq + 0) * 132 + lm] = av.x;
            As[nb][(lkq + 1) * 132 + lm] = av.y;
            As[nb][(lkq + 2) * 132 + lm] = av.z;
            As[nb][(lkq + 3) * 132 + lm] = av.w;
            *(float4*)(&Bs[nb][lkr * 128 + lnq]) = bv;
            __syncthreads();
            buf = nb;
        }
    }

#pragma unroll
    for (int i = 0; i < 8; i++) {
        const int m = m0 + ty * 8 + i;
        const int bb = m >> 9;
        const int s  = m & 511;
#pragma unroll
        for (int jp = 0; jp < 4; jp++) {
            const float2 vv = unpack2(acc2[i][jp]);
            const float vs[2] = {vv.x, vv.y};
#pragma unroll
            for (int q = 0; q < 2; q++) {
                const int n = n0 + tx * 8 + jp * 2 + q;
                const int h  = n / 96;
                const int r  = n - h * 96;
                const int t3 = r >> 5;
                const int d  = r & 31;
                const float v = vs[q] + bias[n];
                float* dst = (t3 == 0) ? g_Q : ((t3 == 1) ? g_K : g_V);
                dst[((size_t)(bb * H_ + h) * S_ + s) * DH_ + d] = v;
            }
        }
    }
}

// ---------------------------------------------------------------------------
// Kernel A2: qsum/ksum over dh.
// ---------------------------------------------------------------------------
__global__ void __launch_bounds__(256) sums_kernel()
{
    const int r = blockIdx.x * 256 + threadIdx.x;
    const float4* q4 = (const float4*)(g_Q + (size_t)r * DH_);
    const float4* k4 = (const float4*)(g_K + (size_t)r * DH_);
    float sq = 0.0f, sk = 0.0f;
#pragma unroll
    for (int u = 0; u < 8; u++) {
        float4 a = q4[u]; sq += (a.x + a.y) + (a.z + a.w);
        float4 c = k4[u]; sk += (c.x + c.y) + (c.z + c.w);
    }
    g_qsum[r] = sq;
    g_ksum[r] = sk;
}

// ---------------------------------------------------------------------------
// Kernel B: folded edge projection (output pre-scaled by SCALE_L2E).
// ---------------------------------------------------------------------------
__global__ void __launch_bounds__(128) radd_kernel(
    const float* __restrict__ P, const float* __restrict__ Wrqk,
    const float* __restrict__ brqk)
{
    __shared__ __align__(16) float pT[128 * 65];   // [e][j], conflict-free
    __shared__ __align__(16) float Wc[128 * 16];   // folded weights [e][h]
    __shared__ float kss[16], qss[16], badd[16];

    const int b  = blockIdx.z;
    const int i  = blockIdx.y;
    const int j0 = blockIdx.x * 64;
    const int tid = threadIdx.x;

    if (tid < 16) {
        kss[tid] = g_ksum[(size_t)(b * H_ + tid) * S_ + i];
        qss[tid] = g_qsum[(size_t)(b * H_ + tid) * S_ + i];
    }
    __syncthreads();

    for (int f = tid; f < 128 * 16; f += 128) {
        const int e = f >> 4;
        const int h = f & 15;
        Wc[f] = Wrqk[e * 32 + 2 * h] * kss[h] + Wrqk[e * 32 + 2 * h + 1] * qss[h];
    }
    if (tid < 16)
        badd[tid] = brqk[2 * tid] * kss[tid] + brqk[2 * tid + 1] * qss[tid];

    // stage p tile transposed, vectorized LDG.128 (16 iterations, high MLP)
    const float4* pg4 = (const float4*)(P + ((size_t)(b * S_ + i) * S_ + j0) * E_);
#pragma unroll 4
    for (int f4 = tid; f4 < 64 * 32; f4 += 128) {
        const float4 v = pg4[f4];
        const int j  = f4 >> 5;
        const int e0 = (f4 & 31) * 4;
        pT[(e0 + 0) * 65 + j] = v.x;
        pT[(e0 + 1) * 65 + j] = v.y;
        pT[(e0 + 2) * 65 + j] = v.z;
        pT[(e0 + 3) * 65 + j] = v.w;
    }
    __syncthreads();

    const int jg = tid & 63;
    const int hg = tid >> 6;

    ull acc2[4];
#pragma unroll
    for (int k = 0; k < 4; k++) acc2[k] = 0ULL;

#pragma unroll 4
    for (int e = 0; e < 128; e++) {
        const float pv = pT[e * 65 + jg];
        const ull pp = pack2(pv, pv);
        const ulonglong2 w01 = *(const ulonglong2*)(Wc + e * 16 + hg * 8);
        const ulonglong2 w23 = *(const ulonglong2*)(Wc + e * 16 + hg * 8 + 4);
        ffma2(acc2[0], pp, w01.x);
        ffma2(acc2[1], pp, w01.y);
        ffma2(acc2[2], pp, w23.x);
        ffma2(acc2[3], pp, w23.y);
    }

#pragma unroll
    for (int k = 0; k < 4; k++) {
        const float2 v = unpack2(acc2[k]);
        const int h0 = hg * 8 + 2 * k;
        const int h1 = h0 + 1;
        g_RADD[((size_t)(b * H_ + h0) * S_ + i) * S_ + j0 + jg] = (v.x + badd[h0]) * SCALE_L2E;
        g_RADD[((size_t)(b * H_ + h1) * S_ + i) * S_ + j0 + jg] = (v.y + badd[h1]) * SCALE_L2E;
    }
}

// ---------------------------------------------------------------------------
// Kernel C: fused attention. Register-prefetch pipeline, transposed v tile,
// j-packed FFMA2 PV microtile, exp2-based online softmax.
// ---------------------------------------------------------------------------
__global__ void __launch_bounds__(256) attn_kernel(
    const int* __restrict__ mask, float* __restrict__ out)
{
    __shared__ __align__(16) float q_s[32 * 68];   // [d][i], pre-scaled by SCALE_L2E
    __shared__ __align__(16) float k_s[32 * 68];   // [d][j]
    __shared__ __align__(16) float v_s[32 * 68];   // [d][j]  (transposed!)
    __shared__ __align__(16) float s_s[64 * 68];   // [i][j] scores -> probs
    __shared__ float alpha_s[64];
    __shared__ float rowl_s[64];

    const int b  = blockIdx.z;
    const int h  = blockIdx.y;
    const int i0 = blockIdx.x * 64;
    const int tid  = threadIdx.x;
    const int lane = tid & 31;
    const int w    = tid >> 5;
    const int tx = tid & 15;        // QK: j-group   | PV: d-pair
    const int ty = tid >> 4;        // QK: i-group   | PV: i-group(4)

    const float maskvalL = -10000.0f * SCALE_L2E;

    const size_t bh = (size_t)(b * H_ + h);
    const float* kg_base = g_K + (bh * S_) * DH_;
    const float* vg_base = g_V + (bh * S_) * DH_;

    // load q tile transposed, pre-scaled
    {
        const float* qg = g_Q + (bh * S_ + i0) * DH_;
#pragma unroll
        for (int u = 0; u < 8; u++) {
            const int f = tid + u * 256;
            const int i = f >> 5;
            const int d = f & 31;
            q_s[d * 68 + i] = qg[f] * SCALE_L2E;
        }
    }

    // stage tile 0 (k,v transposed into smem)
    {
        const float4* kg4 = (const float4*)kg_base;
        const float4* vg4 = (const float4*)vg_base;
#pragma unroll
        for (int u = 0; u < 2; u++) {
            const int f4 = tid + u * 256;
            const int j  = f4 >> 3;
            const int d0 = (f4 & 7) * 4;
            const float4 kv = kg4[f4];
            const float4 vv = vg4[f4];
            k_s[(d0 + 0) * 68 + j] = kv.x;
            k_s[(d0 + 1) * 68 + j] = kv.y;
            k_s[(d0 + 2) * 68 + j] = kv.z;
            k_s[(d0 + 3) * 68 + j] = kv.w;
            v_s[(d0 + 0) * 68 + j] = vv.x;
            v_s[(d0 + 1) * 68 + j] = vv.y;
            v_s[(d0 + 2) * 68 + j] = vv.z;
            v_s[(d0 + 3) * 68 + j] = vv.w;
        }
    }
    __syncthreads();

    float m_run[2], l_run[2];     // softmax state: warp w owns rows w*8.. but
    // we keep 8 rows per warp as before -> need 8 slots
    float m8[8], l8[8];
#pragma unroll
    for (int rr = 0; rr < 8; rr++) { m8[rr] = -1e30f; l8[rr] = 0.0f; }
    (void)m_run; (void)l_run;

    ull accJ[4][2];               // PV accumulators: [i-sub][d-sub], packed (even-j, odd-j)
#pragma unroll
    for (int a = 0; a < 4; a++) { accJ[a][0] = 0ULL; accJ[a][1] = 0ULL; }

    for (int t = 0; t < 8; t++) {
        const int j0 = t * 64;
        const bool hasn = (t < 7);

        // prefetch next k/v tile into registers (latency hidden behind QK/softmax/PV)
        float4 kr[2], vr[2];
        if (hasn) {
            const float4* kg4 = (const float4*)(kg_base + (size_t)(j0 + 64) * DH_);
            const float4* vg4 = (const float4*)(vg_base + (size_t)(j0 + 64) * DH_);
#pragma unroll
            for (int u = 0; u < 2; u++) {
                kr[u] = kg4[tid + u * 256];
                vr[u] = vg4[tid + u * 256];
            }
        }

        // issue RADD + mask loads early (consumed after QK)
        float4 r4[4]; int4 mk[4];
#pragma unroll
        for (int ii = 0; ii < 4; ii++) {
            const int i = i0 + ty * 4 + ii;
            r4[ii] = *(const float4*)(g_RADD + (bh * S_ + i) * S_ + j0 + tx * 4);
            mk[ii] = *(const int4*)(mask + ((size_t)(b * S_ + i)) * S_ + j0 + tx * 4);
        }

        // --- QK^T 64x64, FFMA2 pairs over j ---
        ull acc2[4][2];
#pragma unroll
        for (int a = 0; a < 4; a++) { acc2[a][0] = 0ULL; acc2[a][1] = 0ULL; }

#pragma unroll
        for (int d = 0; d < 32; d++) {
            float av[4];
            *(float4*)(av) = *(const float4*)(q_s + d * 68 + ty * 4);
            const ulonglong2 bq = *(const ulonglong2*)(k_s + d * 68 + tx * 4);
#pragma unroll
            for (int ii = 0; ii < 4; ii++) {
                const ull ap = pack2(av[ii], av[ii]);
                ffma2(acc2[ii][0], ap, bq.x);
                ffma2(acc2[ii][1], ap, bq.y);
            }
        }

        // scores (already scaled) + RADD, mask -> s_s
#pragma unroll
        for (int ii = 0; ii < 4; ii++) {
            const float2 p01 = unpack2(acc2[ii][0]);
            const float2 p23 = unpack2(acc2[ii][1]);
            float4 sv;
            sv.x = (mk[ii].x != 0) ? (p01.x + r4[ii].x) : maskvalL;
            sv.y = (mk[ii].y != 0) ? (p01.y + r4[ii].y) : maskvalL;
            sv.z = (mk[ii].z != 0) ? (p23.x + r4[ii].z) : maskvalL;
            sv.w = (mk[ii].w != 0) ? (p23.y + r4[ii].w) : maskvalL;
            *(float4*)(s_s + (ty * 4 + ii) * 68 + tx * 4) = sv;
        }
        __syncthreads();

        // --- online softmax: warp w owns rows w*8..w*8+7 ---
#pragma unroll
        for (int rr = 0; rr < 8; rr++) {
            const int r = w * 8 + rr;
            const float x0 = s_s[r * 68 + lane];
            const float x1 = s_s[r * 68 + 32 + lane];
            float mx = fmaxf(x0, x1);
#pragma unroll
            for (int off = 16; off > 0; off >>= 1)
                mx = fmaxf(mx, __shfl_xor_sync(0xffffffffu, mx, off));
            const float m_new = fmaxf(m8[rr], mx);
            const float e0 = exp2f(x0 - m_new);
            const float e1 = exp2f(x1 - m_new);
            s_s[r * 68 + lane]      = e0;
            s_s[r * 68 + 32 + lane] = e1;
            float sm = e0 + e1;
#pragma unroll
            for (int off = 16; off > 0; off >>= 1)
                sm += __shfl_xor_sync(0xffffffffu, sm, off);
            const float alpha = exp2f(m8[rr] - m_new);
            l8[rr] = l8[rr] * alpha + sm;
            m8[rr] = m_new;
            if (lane == 0) alpha_s[r] = alpha;
        }
        __syncthreads();

        // --- PV: thread = 4i x 2d, FFMA2 packed over (even j, odd j) ---
        const int ib = ty * 4;
        const int d0 = tx * 2;
#pragma unroll
        for (int ii = 0; ii < 4; ii++) {
            const float a = alpha_s[ib + ii];
            const ull ap = pack2(a, a);
            accJ[ii][0] = fmul2(accJ[ii][0], ap);
            accJ[ii][1] = fmul2(accJ[ii][1], ap);
        }
#pragma unroll 4
        for (int j4 = 0; j4 < 64; j4 += 4) {
            const ulonglong2 v0 = *(const ulonglong2*)(v_s + (d0 + 0) * 68 + j4);
            const ulonglong2 v1 = *(const ulonglong2*)(v_s + (d0 + 1) * 68 + j4);
#pragma unroll
            for (int ii = 0; ii < 4; ii++) {
                const ulonglong2 pp = *(const ulonglong2*)(s_s + (ib + ii) * 68 + j4);
                ffma2(accJ[ii][0], pp.x, v0.x);
                ffma2(accJ[ii][0], pp.y, v0.y);
                ffma2(accJ[ii][1], pp.x, v1.x);
                ffma2(accJ[ii][1], pp.y, v1.y);
            }
        }

        if (hasn) {
            __syncthreads();   // all reads of k_s/v_s/s_s done
#pragma unroll
            for (int u = 0; u < 2; u++) {
                const int f4 = tid + u * 256;
                const int j  = f4 >> 3;
                const int dd = (f4 & 7) * 4;
                k_s[(dd + 0) * 68 + j] = kr[u].x;
                k_s[(dd + 1) * 68 + j] = kr[u].y;
                k_s[(dd + 2) * 68 + j] = kr[u].z;
                k_s[(dd + 3) * 68 + j] = kr[u].w;
                v_s[(dd + 0) * 68 + j] = vr[u].x;
                v_s[(dd + 1) * 68 + j] = vr[u].y;
                v_s[(dd + 2) * 68 + j] = vr[u].z;
                v_s[(dd + 3) * 68 + j] = vr[u].w;
            }
            __syncthreads();   // new tile visible
        }
    }

    // publish per-row l, then epilogue
#pragma unroll
    for (int rr = 0; rr < 8; rr++)
        if (lane == 0) rowl_s[w * 8 + rr] = l8[rr];
    __syncthreads();

    const int ib = ty * 4;
    const int d0 = tx * 2;
#pragma unroll
    for (int ii = 0; ii < 4; ii++) {
        const float l = rowl_s[ib + ii];
        const float2 o0 = unpack2(accJ[ii][0]);
        const float2 o1 = unpack2(accJ[ii][1]);
        float2 res;
        res.x = (o0.x + o0.y) / l;
        res.y = (o1.x + o1.y) / l;
        *(float2*)(out + ((size_t)(b * S_ + i0 + ib + ii)) * D_ + h * DH_ + d0) = res;
    }
}

// ---------------------------------------------------------------------------
extern "C" void kernel_launch(void* const* d_in, const int* in_sizes, int n_in,
                              void* d_out, int out_size)
{
    const float* x     = (const float*)d_in[0];
    const float* p     = (const float*)d_in[1];
    const int*   mask  = (const int*)  d_in[2];
    const float* Wqkv  = (const float*)d_in[3];
    const float* bqkv  = (const float*)d_in[4];
    const float* Wrqk  = (const float*)d_in[5];
    const float* brqk  = (const float*)d_in[6];
    float* out = (float*)d_out;

    (void)in_sizes; (void)n_in; (void)out_size;

    qkv_gemm_kernel<<<dim3(1536 / 128, 2048 / 128), 256>>>(x, Wqkv, bqkv);
    sums_kernel<<<(B_ * H_ * S_) / 256, 256>>>();
    radd_kernel<<<dim3(S_ / 64, S_, B_), 128>>>(p, Wrqk, brqk);
    attn_kernel<<<dim3(S_ / 64, H_, B_), 256>>>(mask, out);
}

// round 9
// speedup vs baseline: 1.2353x; 1.0215x over previous
#include <cuda_runtime.h>
#include <cuda_bf16.h>

#define B_  4
#define S_  512
#define D_  512
#define H_  16
#define DH_ 32
#define E_  128

typedef unsigned long long ull;

// ---- f32x2 packed-math helpers (sm_103a FFMA2 path, PTX-only) -------------
__device__ __forceinline__ ull pack2(float x, float y) {
    ull r; asm("mov.b64 %0, {%1, %2};" : "=l"(r) : "f"(x), "f"(y)); return r;
}
__device__ __forceinline__ void ffma2(ull& d, ull a, ull b) {
    asm("fma.rn.f32x2 %0, %1, %2, %0;" : "+l"(d) : "l"(a), "l"(b));
}
__device__ __forceinline__ ull fmul2(ull a, ull b) {
    ull r; asm("mul.rn.f32x2 %0, %1, %2;" : "=l"(r) : "l"(a), "l"(b)); return r;
}
__device__ __forceinline__ float2 unpack2(ull v) {
    float2 f; asm("mov.b64 {%0, %1}, %2;" : "=f"(f.x), "=f"(f.y) : "l"(v)); return f;
}

// scale * log2(e): scores pre-multiplied so softmax uses exp2f directly.
#define SCALE_L2E (0.10206207261596576f * 1.4426950408889634f)

// fp32 scratch (static device globals; no allocation anywhere)
__device__ float g_Q[B_*H_*S_*DH_];
__device__ float g_K[B_*H_*S_*DH_];
__device__ float g_V[B_*H_*S_*DH_];
__device__ float g_ksum[B_*H_*S_];
__device__ float g_qsum[B_*H_*S_];
__device__ float g_RADD[B_*H_*S_*S_];      // folded edge term * SCALE_L2E, [b,h,i,j]

// ---------------------------------------------------------------------------
// Kernel A: qkv = x @ Wqkv + bqkv  (M=2048, K=512, N=1536). Double-buffered
// 128x128x8 sgemm, FFMA2 inner product.
// ---------------------------------------------------------------------------
__global__ void __launch_bounds__(256) qkv_gemm_kernel(
    const float* __restrict__ X, const float* __restrict__ W,
    const float* __restrict__ bias)
{
    __shared__ __align__(16) float As[2][8 * 132];
    __shared__ __align__(16) float Bs[2][8 * 128];

    const int m0 = blockIdx.y * 128;
    const int n0 = blockIdx.x * 128;
    const int tid = threadIdx.x;
    const int tx = tid & 15;
    const int ty = tid >> 4;

    const int lm  = tid >> 1;
    const int lkq = (tid & 1) * 4;
    const int lkr = tid >> 5;
    const int lnq = (tid & 31) * 4;

    const float* Ag = X + (size_t)(m0 + lm) * 512 + lkq;
    const float* Bg = W + (size_t)lkr * 1536 + n0 + lnq;

    ull acc2[8][4];
#pragma unroll
    for (int i = 0; i < 8; i++)
#pragma unroll
        for (int j = 0; j < 4; j++) acc2[i][j] = 0ULL;

    {
        float4 av = *(const float4*)(Ag);
        float4 bv = *(const float4*)(Bg);
        As[0][(lkq + 0) * 132 + lm] = av.x;
        As[0][(lkq + 1) * 132 + lm] = av.y;
        As[0][(lkq + 2) * 132 + lm] = av.z;
        As[0][(lkq + 3) * 132 + lm] = av.w;
        *(float4*)(&Bs[0][lkr * 128 + lnq]) = bv;
    }
    __syncthreads();

    int buf = 0;
    for (int k0 = 0; k0 < 512; k0 += 8) {
        const bool has_next = (k0 + 8) < 512;
        float4 av, bv;
        if (has_next) {
            av = *(const float4*)(Ag + k0 + 8);
            bv = *(const float4*)(Bg + (size_t)(k0 + 8) * 1536);
        }

        const float* Asb = As[buf];
        const float* Bsb = Bs[buf];
#pragma unroll
        for (int kk = 0; kk < 8; kk++) {
            float a[8];
            *(float4*)(a)     = *(const float4*)(Asb + kk * 132 + ty * 8);
            *(float4*)(a + 4) = *(const float4*)(Asb + kk * 132 + ty * 8 + 4);
            ulonglong2 b01 = *(const ulonglong2*)(Bsb + kk * 128 + tx * 8);
            ulonglong2 b23 = *(const ulonglong2*)(Bsb + kk * 128 + tx * 8 + 4);
            ull bp0 = b01.x, bp1 = b01.y, bp2 = b23.x, bp3 = b23.y;
#pragma unroll
            for (int i = 0; i < 8; i++) {
                const ull ap = pack2(a[i], a[i]);
                ffma2(acc2[i][0], ap, bp0);
                ffma2(acc2[i][1], ap, bp1);
                ffma2(acc2[i][2], ap, bp2);
                ffma2(acc2[i][3], ap, bp3);
            }
        }

        if (has_next) {
            const int nb = buf ^ 1;
            As[nb][(lkq + 0) * 132 + lm] = av.x;
            As[nb][(lkq + 1) * 132 + lm] = av.y;
            As[nb][(lkq + 2) * 132 + lm] = av.z;
            As[nb][(lkq + 3) * 132 + lm] = av.w;
            *(float4*)(&Bs[nb][lkr * 128 + lnq]) = bv;
            __syncthreads();
            buf = nb;
        }
    }

#pragma unroll
    for (int i = 0; i < 8; i++) {
        const int m = m0 + ty * 8 + i;
        const int bb = m >> 9;
        const int s  = m & 511;
#pragma unroll
        for (int jp = 0; jp < 4; jp++) {
            const float2 vv = unpack2(acc2[i][jp]);
            const float vs[2] = {vv.x, vv.y};
#pragma unroll
            for (int q = 0; q < 2; q++) {
                const int n = n0 + tx * 8 + jp * 2 + q;
                const int h  = n / 96;
                const int r  = n - h * 96;
                const int t3 = r >> 5;
                const int d  = r & 31;
                const float v = vs[q] + bias[n];
                float* dst = (t3 == 0) ? g_Q : ((t3 == 1) ? g_K : g_V);
                dst[((size_t)(bb * H_ + h) * S_ + s) * DH_ + d] = v;
            }
        }
    }
}

// ---------------------------------------------------------------------------
// Kernel A2: qsum/ksum over dh.
// ---------------------------------------------------------------------------
__global__ void __launch_bounds__(256) sums_kernel()
{
    const int r = blockIdx.x * 256 + threadIdx.x;
    const float4* q4 = (const float4*)(g_Q + (size_t)r * DH_);
    const float4* k4 = (const float4*)(g_K + (size_t)r * DH_);
    float sq = 0.0f, sk = 0.0f;
#pragma unroll
    for (int u = 0; u < 8; u++) {
        float4 a = q4[u]; sq += (a.x + a.y) + (a.z + a.w);
        float4 c = k4[u]; sk += (c.x + c.y) + (c.z + c.w);
    }
    g_qsum[r] = sq;
    g_ksum[r] = sk;
}

// ---------------------------------------------------------------------------
// Kernel B: folded edge projection (output pre-scaled by SCALE_L2E).
// CTA = (b, i) full 512-j row, 256 threads, 8 chunks of 64 j.
// Register-prefetch pipeline: LDG chunk c+1 in flight during chunk-c compute.
// Thread = 1 j x 4 heads (hg warp-uniform -> Wc LDS.128 is broadcast).
// ---------------------------------------------------------------------------
__global__ void __launch_bounds__(256) radd_kernel(
    const float* __restrict__ P, const float* __restrict__ Wrqk,
    const float* __restrict__ brqk)
{
    __shared__ __align__(16) float pT[128 * 65];   // [e][j], conflict-free (33.3 KB)
    __shared__ __align__(16) float Wc[128 * 16];   // folded weights [e][h] (8 KB)
    __shared__ float kss[16], qss[16], badd[16];

    const int i  = blockIdx.x;
    const int b  = blockIdx.y;
    const int tid = threadIdx.x;

    if (tid < 16) {
        kss[tid] = g_ksum[(size_t)(b * H_ + tid) * S_ + i];
        qss[tid] = g_qsum[(size_t)(b * H_ + tid) * S_ + i];
    }
    __syncthreads();

    // folded weights + bias (once per (b,i) row)
#pragma unroll
    for (int u = 0; u < 8; u++) {
        const int f = tid + u * 256;
        const int e = f >> 4;
        const int h = f & 15;
        Wc[f] = Wrqk[e * 32 + 2 * h] * kss[h] + Wrqk[e * 32 + 2 * h + 1] * qss[h];
    }
    if (tid < 16)
        badd[tid] = brqk[2 * tid] * kss[tid] + brqk[2 * tid + 1] * qss[tid];

    const float4* pg4 = (const float4*)(P + ((size_t)(b * S_ + i)) * S_ * E_);

    // stage chunk 0: 64j x 128e = 2048 float4, 8 per thread
    {
#pragma unroll
        for (int u = 0; u < 8; u++) {
            const int f4 = tid + u * 256;
            const float4 v = pg4[f4];
            const int j  = f4 >> 5;
            const int e0 = (f4 & 31) * 4;
            pT[(e0 + 0) * 65 + j] = v.x;
            pT[(e0 + 1) * 65 + j] = v.y;
            pT[(e0 + 2) * 65 + j] = v.z;
            pT[(e0 + 3) * 65 + j] = v.w;
        }
    }
    __syncthreads();

    const int jg = tid & 63;     // j within chunk
    const int hg = tid >> 6;     // 0..3 -> heads hg*4 .. hg*4+3 (warp-uniform)

    for (int c = 0; c < 8; c++) {
        const bool hasn = (c < 7);
        float4 pr[8];
        if (hasn) {
#pragma unroll
            for (int u = 0; u < 8; u++)
                pr[u] = pg4[(c + 1) * 2048 + tid + u * 256];
        }

        ull acc2[2];
        acc2[0] = 0ULL; acc2[1] = 0ULL;

#pragma unroll 4
        for (int e = 0; e < 128; e++) {
            const float pv = pT[e * 65 + jg];
            const ull pp = pack2(pv, pv);
            const ulonglong2 w01 = *(const ulonglong2*)(Wc + e * 16 + hg * 4);
            ffma2(acc2[0], pp, w01.x);
            ffma2(acc2[1], pp, w01.y);
        }

        const int jglob = c * 64 + jg;
#pragma unroll
        for (int k = 0; k < 2; k++) {
            const float2 v = unpack2(acc2[k]);
            const int h0 = hg * 4 + 2 * k;
            const int h1 = h0 + 1;
            g_RADD[((size_t)(b * H_ + h0) * S_ + i) * S_ + jglob] = (v.x + badd[h0]) * SCALE_L2E;
            g_RADD[((size_t)(b * H_ + h1) * S_ + i) * S_ + jglob] = (v.y + badd[h1]) * SCALE_L2E;
        }

        if (hasn) {
            __syncthreads();   // all reads of pT for chunk c done
#pragma unroll
            for (int u = 0; u < 8; u++) {
                const int f4 = tid + u * 256;
                const int j  = f4 >> 5;
                const int e0 = (f4 & 31) * 4;
                pT[(e0 + 0) * 65 + j] = pr[u].x;
                pT[(e0 + 1) * 65 + j] = pr[u].y;
                pT[(e0 + 2) * 65 + j] = pr[u].z;
                pT[(e0 + 3) * 65 + j] = pr[u].w;
            }
            __syncthreads();   // new chunk visible
        }
    }
}

// ---------------------------------------------------------------------------
// Kernel C: fused attention. QK 4i x 4j microtile, softmax fully in
// registers (half-warp shuffles; QK i-ownership == PV i-ownership so m/l/α
// never leave the thread). Probs hit smem exactly once. 3 barriers/tile.
// ---------------------------------------------------------------------------
__global__ void __launch_bounds__(256) attn_kernel(
    const int* __restrict__ mask, float* __restrict__ out)
{
    __shared__ __align__(16) float q_s[32 * 68];   // [d][i], pre-scaled by SCALE_L2E
    __shared__ __align__(16) float k_s[32 * 68];   // [d][j]
    __shared__ __align__(16) float v_s[32 * 68];   // [d][j]
    __shared__ __align__(16) float s_s[64 * 68];   // [i][j] probs only

    const int b  = blockIdx.z;
    const int h  = blockIdx.y;
    const int i0 = blockIdx.x * 64;
    const int tid  = threadIdx.x;
    const int tx = tid & 15;        // j-group (QK) / d-pair (PV)
    const int ty = tid >> 4;        // i-group: rows ty*4 .. ty*4+3 (QK AND PV)

    const float maskvalL = -10000.0f * SCALE_L2E;

    const size_t bh = (size_t)(b * H_ + h);
    const float* kg_base = g_K + (bh * S_) * DH_;
    const float* vg_base = g_V + (bh * S_) * DH_;

    // load q tile transposed, pre-scaled
    {
        const float* qg = g_Q + (bh * S_ + i0) * DH_;
#pragma unroll
        for (int u = 0; u < 8; u++) {
            const int f = tid + u * 256;
            const int i = f >> 5;
            const int d = f & 31;
            q_s[d * 68 + i] = qg[f] * SCALE_L2E;
        }
    }

    // stage tile 0 (k,v transposed)
    {
        const float4* kg4 = (const float4*)kg_base;
        const float4* vg4 = (const float4*)vg_base;
#pragma unroll
        for (int u = 0; u < 2; u++) {
            const int f4 = tid + u * 256;
            const int j  = f4 >> 3;
            const int d0 = (f4 & 7) * 4;
            const float4 kv = kg4[f4];
            const float4 vv = vg4[f4];
            k_s[(d0 + 0) * 68 + j] = kv.x;
            k_s[(d0 + 1) * 68 + j] = kv.y;
            k_s[(d0 + 2) * 68 + j] = kv.z;
            k_s[(d0 + 3) * 68 + j] = kv.w;
            v_s[(d0 + 0) * 68 + j] = vv.x;
            v_s[(d0 + 1) * 68 + j] = vv.y;
            v_s[(d0 + 2) * 68 + j] = vv.z;
            v_s[(d0 + 3) * 68 + j] = vv.w;
        }
    }
    __syncthreads();

    float m4[4], l4[4];
#pragma unroll
    for (int ii = 0; ii < 4; ii++) { m4[ii] = -1e30f; l4[ii] = 0.0f; }

    ull accJ[4][2];                 // PV accumulators: [i-sub][d-sub]
#pragma unroll
    for (int a = 0; a < 4; a++) { accJ[a][0] = 0ULL; accJ[a][1] = 0ULL; }

    for (int t = 0; t < 8; t++) {
        const int j0 = t * 64;
        const bool hasn = (t < 7);

        // prefetch next k/v tile into registers
        float4 kr[2], vr[2];
        if (hasn) {
            const float4* kg4 = (const float4*)(kg_base + (size_t)(j0 + 64) * DH_);
            const float4* vg4 = (const float4*)(vg_base + (size_t)(j0 + 64) * DH_);
#pragma unroll
            for (int u = 0; u < 2; u++) {
                kr[u] = kg4[tid + u * 256];
                vr[u] = vg4[tid + u * 256];
            }
        }

        // prefetch RADD + mask (consumed after QK)
        float4 r4[4]; int4 mk[4];
#pragma unroll
        for (int ii = 0; ii < 4; ii++) {
            const int i = i0 + ty * 4 + ii;
            r4[ii] = *(const float4*)(g_RADD + (bh * S_ + i) * S_ + j0 + tx * 4);
            mk[ii] = *(const int4*)(mask + ((size_t)(b * S_ + i)) * S_ + j0 + tx * 4);
        }

        // --- QK^T 64x64, FFMA2 pairs over j ---
        ull acc2[4][2];
#pragma unroll
        for (int a = 0; a < 4; a++) { acc2[a][0] = 0ULL; acc2[a][1] = 0ULL; }

#pragma unroll
        for (int d = 0; d < 32; d++) {
            float av[4];
            *(float4*)(av) = *(const float4*)(q_s + d * 68 + ty * 4);
            const ulonglong2 bq = *(const ulonglong2*)(k_s + d * 68 + tx * 4);
#pragma unroll
            for (int ii = 0; ii < 4; ii++) {
                const ull ap = pack2(av[ii], av[ii]);
                ffma2(acc2[ii][0], ap, bq.x);
                ffma2(acc2[ii][1], ap, bq.y);
            }
        }

        // --- softmax fully in registers (reduce across the 16-lane j-group) ---
#pragma unroll
        for (int ii = 0; ii < 4; ii++) {
            const float2 p01 = unpack2(acc2[ii][0]);
            const float2 p23 = unpack2(acc2[ii][1]);
            float x0 = (mk[ii].x != 0) ? (p01.x + r4[ii].x) : maskvalL;
            float x1 = (mk[ii].y != 0) ? (p01.y + r4[ii].y) : maskvalL;
            float x2 = (mk[ii].z != 0) ? (p23.x + r4[ii].z) : maskvalL;
            float x3 = (mk[ii].w != 0) ? (p23.y + r4[ii].w) : maskvalL;

            float mx = fmaxf(fmaxf(x0, x1), fmaxf(x2, x3));
#pragma unroll
            for (int off = 8; off > 0; off >>= 1)   // xor<=8 stays in 16-lane half
                mx = fmaxf(mx, __shfl_xor_sync(0xffffffffu, mx, off));

            const float m_new = fmaxf(m4[ii], mx);
            const float e0 = exp2f(x0 - m_new);
            const float e1 = exp2f(x1 - m_new);
            const float e2 = exp2f(x2 - m_new);
            const float e3 = exp2f(x3 - m_new);

            float sm = (e0 + e1) + (e2 + e3);
#pragma unroll
            for (int off = 8; off > 0; off >>= 1)
                sm += __shfl_xor_sync(0xffffffffu, sm, off);

            const float alpha = exp2f(m4[ii] - m_new);
            l4[ii] = l4[ii] * alpha + sm;
            m4[ii] = m_new;

            // rescale this row's PV accumulator (same-thread ownership)
            const ull ap = pack2(alpha, alpha);
            accJ[ii][0] = fmul2(accJ[ii][0], ap);
            accJ[ii][1] = fmul2(accJ[ii][1], ap);

            // probs to smem (single touch)
            *(float4*)(s_s + (ty * 4 + ii) * 68 + tx * 4) = make_float4(e0, e1, e2, e3);
        }
        __syncthreads();   // probs visible; QK done CTA-wide

        // --- PV: thread = 4i x 2d, FFMA2 packed over (even j, odd j) ---
        const int ib = ty * 4;
        const int d0 = tx * 2;
#pragma unroll 4
        for (int j4 = 0; j4 < 64; j4 += 4) {
            const ulonglong2 v0 = *(const ulonglong2*)(v_s + (d0 + 0) * 68 + j4);
            const ulonglong2 v1 = *(const ulonglong2*)(v_s + (d0 + 1) * 68 + j4);
#pragma unroll
            for (int ii = 0; ii < 4; ii++) {
                const ulonglong2 pp = *(const ulonglong2*)(s_s + (ib + ii) * 68 + j4);
                ffma2(accJ[ii][0], pp.x, v0.x);
                ffma2(accJ[ii][0], pp.y, v0.y);
                ffma2(accJ[ii][1], pp.x, v1.x);
                ffma2(accJ[ii][1], pp.y, v1.y);
            }
        }

        if (hasn) {
            __syncthreads();   // all reads of k_s/v_s/s_s done
#pragma unroll
            for (int u = 0; u < 2; u++) {
                const int f4 = tid + u * 256;
                const int j  = f4 >> 3;
                const int dd = (f4 & 7) * 4;
                k_s[(dd + 0) * 68 + j] = kr[u].x;
                k_s[(dd + 1) * 68 + j] = kr[u].y;
                k_s[(dd + 2) * 68 + j] = kr[u].z;
                k_s[(dd + 3) * 68 + j] = kr[u].w;
                v_s[(dd + 0) * 68 + j] = vr[u].x;
                v_s[(dd + 1) * 68 + j] = vr[u].y;
                v_s[(dd + 2) * 68 + j] = vr[u].z;
                v_s[(dd + 3) * 68 + j] = vr[u].w;
            }
            __syncthreads();   // new tile visible
        }
    }

    // epilogue: l lives in-thread (replicated across the 16-lane j-group)
    const int ib = ty * 4;
    const int d0 = tx * 2;
#pragma unroll
    for (int ii = 0; ii < 4; ii++) {
        const float inv = 1.0f / l4[ii];
        const float2 o0 = unpack2(accJ[ii][0]);
        const float2 o1 = unpack2(accJ[ii][1]);
        float2 res;
        res.x = (o0.x + o0.y) * inv;
        res.y = (o1.x + o1.y) * inv;
        *(float2*)(out + ((size_t)(b * S_ + i0 + ib + ii)) * D_ + h * DH_ + d0) = res;
    }
}

// ---------------------------------------------------------------------------
extern "C" void kernel_launch(void* const* d_in, const int* in_sizes, int n_in,
                              void* d_out, int out_size)
{
    const float* x     = (const float*)d_in[0];
    const float* p     = (const float*)d_in[1];
    const int*   mask  = (const int*)  d_in[2];
    const float* Wqkv  = (const float*)d_in[3];
    const float* bqkv  = (const float*)d_in[4];
    const float* Wrqk  = (const float*)d_in[5];
    const float* brqk  = (const float*)d_in[6];
    float* out = (float*)d_out;

    (void)in_sizes; (void)n_in; (void)out_size;

    qkv_gemm_kernel<<<dim3(1536 / 128, 2048 / 128), 256>>>(x, Wqkv, bqkv);
    sums_kernel<<<(B_ * H_ * S_) / 256, 256>>>();
    radd_kernel<<<dim3(S_, B_), 256>>>(p, Wrqk, brqk);
    attn_kernel<<<dim3(S_ / 64, H_, B_), 256>>>(mask, out);
}

// round 10
// speedup vs baseline: 1.2381x; 1.0022x over previous
#include <cuda_runtime.h>
#include <cuda_bf16.h>

#define B_  4
#define S_  512
#define D_  512
#define H_  16
#define DH_ 32
#define E_  128

typedef unsigned long long ull;

// ---- f32x2 packed-math helpers (sm_103a FFMA2 path, PTX-only) -------------
__device__ __forceinline__ ull pack2(float x, float y) {
    ull r; asm("mov.b64 %0, {%1, %2};" : "=l"(r) : "f"(x), "f"(y)); return r;
}
__device__ __forceinline__ void ffma2(ull& d, ull a, ull b) {
    asm("fma.rn.f32x2 %0, %1, %2, %0;" : "+l"(d) : "l"(a), "l"(b));
}
__device__ __forceinline__ ull fmul2(ull a, ull b) {
    ull r; asm("mul.rn.f32x2 %0, %1, %2;" : "=l"(r) : "l"(a), "l"(b)); return r;
}
__device__ __forceinline__ float2 unpack2(ull v) {
    float2 f; asm("mov.b64 {%0, %1}, %2;" : "=f"(f.x), "=f"(f.y) : "l"(v)); return f;
}

// scale * log2(e): scores pre-multiplied so softmax uses exp2f directly.
#define SCALE_L2E (0.10206207261596576f * 1.4426950408889634f)

// fp32 scratch (static device globals; no allocation anywhere)
__device__ float g_Q[B_*H_*S_*DH_];
__device__ float g_K[B_*H_*S_*DH_];
__device__ float g_V[B_*H_*S_*DH_];
__device__ float g_ksum[B_*H_*S_];
__device__ float g_qsum[B_*H_*S_];
__device__ float g_RADD[B_*H_*S_*S_];      // folded edge term * SCALE_L2E, [b,h,i,j]

// ---------------------------------------------------------------------------
// Kernel A: qkv = x @ Wqkv + bqkv  (M=2048, K=512, N=1536). Double-buffered
// 128x128x8 sgemm, FFMA2 inner product.
// ---------------------------------------------------------------------------
__global__ void __launch_bounds__(256) qkv_gemm_kernel(
    const float* __restrict__ X, const float* __restrict__ W,
    const float* __restrict__ bias)
{
    __shared__ __align__(16) float As[2][8 * 132];
    __shared__ __align__(16) float Bs[2][8 * 128];

    const int m0 = blockIdx.y * 128;
    const int n0 = blockIdx.x * 128;
    const int tid = threadIdx.x;
    const int tx = tid & 15;
    const int ty = tid >> 4;

    const int lm  = tid >> 1;
    const int lkq = (tid & 1) * 4;
    const int lkr = tid >> 5;
    const int lnq = (tid & 31) * 4;

    const float* Ag = X + (size_t)(m0 + lm) * 512 + lkq;
    const float* Bg = W + (size_t)lkr * 1536 + n0 + lnq;

    ull acc2[8][4];
#pragma unroll
    for (int i = 0; i < 8; i++)
#pragma unroll
        for (int j = 0; j < 4; j++) acc2[i][j] = 0ULL;

    {
        float4 av = *(const float4*)(Ag);
        float4 bv = *(const float4*)(Bg);
        As[0][(lkq + 0) * 132 + lm] = av.x;
        As[0][(lkq + 1) * 132 + lm] = av.y;
        As[0][(lkq + 2) * 132 + lm] = av.z;
        As[0][(lkq + 3) * 132 + lm] = av.w;
        *(float4*)(&Bs[0][lkr * 128 + lnq]) = bv;
    }
    __syncthreads();

    int buf = 0;
    for (int k0 = 0; k0 < 512; k0 += 8) {
        const bool has_next = (k0 + 8) < 512;
        float4 av, bv;
        if (has_next) {
            av = *(const float4*)(Ag + k0 + 8);
            bv = *(const float4*)(Bg + (size_t)(k0 + 8) * 1536);
        }

        const float* Asb = As[buf];
        const float* Bsb = Bs[buf];
#pragma unroll
        for (int kk = 0; kk < 8; kk++) {
            float a[8];
            *(float4*)(a)     = *(const float4*)(Asb + kk * 132 + ty * 8);
            *(float4*)(a + 4) = *(const float4*)(Asb + kk * 132 + ty * 8 + 4);
            ulonglong2 b01 = *(const ulonglong2*)(Bsb + kk * 128 + tx * 8);
            ulonglong2 b23 = *(const ulonglong2*)(Bsb + kk * 128 + tx * 8 + 4);
            ull bp0 = b01.x, bp1 = b01.y, bp2 = b23.x, bp3 = b23.y;
#pragma unroll
            for (int i = 0; i < 8; i++) {
                const ull ap = pack2(a[i], a[i]);
                ffma2(acc2[i][0], ap, bp0);
                ffma2(acc2[i][1], ap, bp1);
                ffma2(acc2[i][2], ap, bp2);
                ffma2(acc2[i][3], ap, bp3);
            }
        }

        if (has_next) {
            const int nb = buf ^ 1;
            As[nb][(lkq + 0) * 132 + lm] = av.x;
            As[nb][(lkq + 1) * 132 + lm] = av.y;
            As[nb][(lkq + 2) * 132 + lm] = av.z;
            As[nb][(lkq + 3) * 132 + lm] = av.w;
            *(float4*)(&Bs[nb][lkr * 128 + lnq]) = bv;
            __syncthreads();
            buf = nb;
        }
    }

#pragma unroll
    for (int i = 0; i < 8; i++) {
        const int m = m0 + ty * 8 + i;
        const int bb = m >> 9;
        const int s  = m & 511;
#pragma unroll
        for (int jp = 0; jp < 4; jp++) {
            const float2 vv = unpack2(acc2[i][jp]);
            const float vs[2] = {vv.x, vv.y};
#pragma unroll
            for (int q = 0; q < 2; q++) {
                const int n = n0 + tx * 8 + jp * 2 + q;
                const int h  = n / 96;
                const int r  = n - h * 96;
                const int t3 = r >> 5;
                const int d  = r & 31;
                const float v = vs[q] + bias[n];
                float* dst = (t3 == 0) ? g_Q : ((t3 == 1) ? g_K : g_V);
                dst[((size_t)(bb * H_ + h) * S_ + s) * DH_ + d] = v;
            }
        }
    }
}

// ---------------------------------------------------------------------------
// Kernel A2: qsum/ksum over dh.
// ---------------------------------------------------------------------------
__global__ void __launch_bounds__(256) sums_kernel()
{
    const int r = blockIdx.x * 256 + threadIdx.x;
    const float4* q4 = (const float4*)(g_Q + (size_t)r * DH_);
    const float4* k4 = (const float4*)(g_K + (size_t)r * DH_);
    float sq = 0.0f, sk = 0.0f;
#pragma unroll
    for (int u = 0; u < 8; u++) {
        float4 a = q4[u]; sq += (a.x + a.y) + (a.z + a.w);
        float4 c = k4[u]; sk += (c.x + c.y) + (c.z + c.w);
    }
    g_qsum[r] = sq;
    g_ksum[r] = sk;
}

// ---------------------------------------------------------------------------
// Kernel B: folded edge projection (output pre-scaled by SCALE_L2E).
// CTA = (b, i) full 512-j row, 256 threads, 8 chunks of 64 j.
// Register-prefetch pipeline: LDG chunk c+1 in flight during chunk-c compute.
// Thread = 1 j x 4 heads (hg warp-uniform -> Wc LDS.128 is broadcast).
// ---------------------------------------------------------------------------
__global__ void __launch_bounds__(256) radd_kernel(
    const float* __restrict__ P, const float* __restrict__ Wrqk,
    const float* __restrict__ brqk)
{
    __shared__ __align__(16) float pT[128 * 65];   // [e][j], conflict-free (33.3 KB)
    __shared__ __align__(16) float Wc[128 * 16];   // folded weights [e][h] (8 KB)
    __shared__ float kss[16], qss[16], badd[16];

    const int i  = blockIdx.x;
    const int b  = blockIdx.y;
    const int tid = threadIdx.x;

    if (tid < 16) {
        kss[tid] = g_ksum[(size_t)(b * H_ + tid) * S_ + i];
        qss[tid] = g_qsum[(size_t)(b * H_ + tid) * S_ + i];
    }
    __syncthreads();

    // folded weights + bias (once per (b,i) row)
#pragma unroll
    for (int u = 0; u < 8; u++) {
        const int f = tid + u * 256;
        const int e = f >> 4;
        const int h = f & 15;
        Wc[f] = Wrqk[e * 32 + 2 * h] * kss[h] + Wrqk[e * 32 + 2 * h + 1] * qss[h];
    }
    if (tid < 16)
        badd[tid] = brqk[2 * tid] * kss[tid] + brqk[2 * tid + 1] * qss[tid];

    const float4* pg4 = (const float4*)(P + ((size_t)(b * S_ + i)) * S_ * E_);

    // stage chunk 0: 64j x 128e = 2048 float4, 8 per thread
    {
#pragma unroll
        for (int u = 0; u < 8; u++) {
            const int f4 = tid + u * 256;
            const float4 v = pg4[f4];
            const int j  = f4 >> 5;
            const int e0 = (f4 & 31) * 4;
            pT[(e0 + 0) * 65 + j] = v.x;
            pT[(e0 + 1) * 65 + j] = v.y;
            pT[(e0 + 2) * 65 + j] = v.z;
            pT[(e0 + 3) * 65 + j] = v.w;
        }
    }
    __syncthreads();

    const int jg = tid & 63;     // j within chunk
    const int hg = tid >> 6;     // 0..3 -> heads hg*4 .. hg*4+3 (warp-uniform)

    for (int c = 0; c < 8; c++) {
        const bool hasn = (c < 7);
        float4 pr[8];
        if (hasn) {
#pragma unroll
            for (int u = 0; u < 8; u++)
                pr[u] = pg4[(c + 1) * 2048 + tid + u * 256];
        }

        ull acc2[2];
        acc2[0] = 0ULL; acc2[1] = 0ULL;

#pragma unroll 4
        for (int e = 0; e < 128; e++) {
            const float pv = pT[e * 65 + jg];
            const ull pp = pack2(pv, pv);
            const ulonglong2 w01 = *(const ulonglong2*)(Wc + e * 16 + hg * 4);
            ffma2(acc2[0], pp, w01.x);
            ffma2(acc2[1], pp, w01.y);
        }

        const int jglob = c * 64 + jg;
#pragma unroll
        for (int k = 0; k < 2; k++) {
            const float2 v = unpack2(acc2[k]);
            const int h0 = hg * 4 + 2 * k;
            const int h1 = h0 + 1;
            g_RADD[((size_t)(b * H_ + h0) * S_ + i) * S_ + jglob] = (v.x + badd[h0]) * SCALE_L2E;
            g_RADD[((size_t)(b * H_ + h1) * S_ + i) * S_ + jglob] = (v.y + badd[h1]) * SCALE_L2E;
        }

        if (hasn) {
            __syncthreads();   // all reads of pT for chunk c done
#pragma unroll
            for (int u = 0; u < 8; u++) {
                const int f4 = tid + u * 256;
                const int j  = f4 >> 5;
                const int e0 = (f4 & 31) * 4;
                pT[(e0 + 0) * 65 + j] = pr[u].x;
                pT[(e0 + 1) * 65 + j] = pr[u].y;
                pT[(e0 + 2) * 65 + j] = pr[u].z;
                pT[(e0 + 3) * 65 + j] = pr[u].w;
            }
            __syncthreads();   // new chunk visible
        }
    }
}

// ---------------------------------------------------------------------------
// Kernel C: fused attention. QK 4i x 4j microtile, softmax fully in
// registers (half-warp shuffles; QK i-ownership == PV i-ownership so m/l/α
// never leave the thread). Probs hit smem exactly once. 3 barriers/tile.
// ---------------------------------------------------------------------------
__global__ void __launch_bounds__(256) attn_kernel(
    const int* __restrict__ mask, float* __restrict__ out)
{
    __shared__ __align__(16) float q_s[32 * 68];   // [d][i], pre-scaled by SCALE_L2E
    __shared__ __align__(16) float k_s[32 * 68];   // [d][j]
    __shared__ __align__(16) float v_s[32 * 68];   // [d][j]
    __shared__ __align__(16) float s_s[64 * 68];   // [i][j] probs only

    const int b  = blockIdx.z;
    const int h  = blockIdx.y;
    const int i0 = blockIdx.x * 64;
    const int tid  = threadIdx.x;
    const int tx = tid & 15;        // j-group (QK) / d-pair (PV)
    const int ty = tid >> 4;        // i-group: rows ty*4 .. ty*4+3 (QK AND PV)

    const float maskvalL = -10000.0f * SCALE_L2E;

    const size_t bh = (size_t)(b * H_ + h);
    const float* kg_base = g_K + (bh * S_) * DH_;
    const float* vg_base = g_V + (bh * S_) * DH_;

    // load q tile transposed, pre-scaled
    {
        const float* qg = g_Q + (bh * S_ + i0) * DH_;
#pragma unroll
        for (int u = 0; u < 8; u++) {
            const int f = tid + u * 256;
            const int i = f >> 5;
            const int d = f & 31;
            q_s[d * 68 + i] = qg[f] * SCALE_L2E;
        }
    }

    // stage tile 0 (k,v transposed)
    {
        const float4* kg4 = (const float4*)kg_base;
        const float4* vg4 = (const float4*)vg_base;
#pragma unroll
        for (int u = 0; u < 2; u++) {
            const int f4 = tid + u * 256;
            const int j  = f4 >> 3;
            const int d0 = (f4 & 7) * 4;
            const float4 kv = kg4[f4];
            const float4 vv = vg4[f4];
            k_s[(d0 + 0) * 68 + j] = kv.x;
            k_s[(d0 + 1) * 68 + j] = kv.y;
            k_s[(d0 + 2) * 68 + j] = kv.z;
            k_s[(d0 + 3) * 68 + j] = kv.w;
            v_s[(d0 + 0) * 68 + j] = vv.x;
            v_s[(d0 + 1) * 68 + j] = vv.y;
            v_s[(d0 + 2) * 68 + j] = vv.z;
            v_s[(d0 + 3) * 68 + j] = vv.w;
        }
    }
    __syncthreads();

    float m4[4], l4[4];
#pragma unroll
    for (int ii = 0; ii < 4; ii++) { m4[ii] = -1e30f; l4[ii] = 0.0f; }

    ull accJ[4][2];                 // PV accumulators: [i-sub][d-sub]
#pragma unroll
    for (int a = 0; a < 4; a++) { accJ[a][0] = 0ULL; accJ[a][1] = 0ULL; }

    for (int t = 0; t < 8; t++) {
        const int j0 = t * 64;
        const bool hasn = (t < 7);

        // prefetch next k/v tile into registers
        float4 kr[2], vr[2];
        if (hasn) {
            const float4* kg4 = (const float4*)(kg_base + (size_t)(j0 + 64) * DH_);
            const float4* vg4 = (const float4*)(vg_base + (size_t)(j0 + 64) * DH_);
#pragma unroll
            for (int u = 0; u < 2; u++) {
                kr[u] = kg4[tid + u * 256];
                vr[u] = vg4[tid + u * 256];
            }
        }

        // prefetch RADD + mask (consumed after QK)
        float4 r4[4]; int4 mk[4];
#pragma unroll
        for (int ii = 0; ii < 4; ii++) {
            const int i = i0 + ty * 4 + ii;
            r4[ii] = *(const float4*)(g_RADD + (bh * S_ + i) * S_ + j0 + tx * 4);
            mk[ii] = *(const int4*)(mask + ((size_t)(b * S_ + i)) * S_ + j0 + tx * 4);
        }

        // --- QK^T 64x64, FFMA2 pairs over j ---
        ull acc2[4][2];
#pragma unroll
        for (int a = 0; a < 4; a++) { acc2[a][0] = 0ULL; acc2[a][1] = 0ULL; }

#pragma unroll
        for (int d = 0; d < 32; d++) {
            float av[4];
            *(float4*)(av) = *(const float4*)(q_s + d * 68 + ty * 4);
            const ulonglong2 bq = *(const ulonglong2*)(k_s + d * 68 + tx * 4);
#pragma unroll
            for (int ii = 0; ii < 4; ii++) {
                const ull ap = pack2(av[ii], av[ii]);
                ffma2(acc2[ii][0], ap, bq.x);
                ffma2(acc2[ii][1], ap, bq.y);
            }
        }

        // --- softmax fully in registers (reduce across the 16-lane j-group) ---
#pragma unroll
        for (int ii = 0; ii < 4; ii++) {
            const float2 p01 = unpack2(acc2[ii][0]);
            const float2 p23 = unpack2(acc2[ii][1]);
            float x0 = (mk[ii].x != 0) ? (p01.x + r4[ii].x) : maskvalL;
            float x1 = (mk[ii].y != 0) ? (p01.y + r4[ii].y) : maskvalL;
            float x2 = (mk[ii].z != 0) ? (p23.x + r4[ii].z) : maskvalL;
            float x3 = (mk[ii].w != 0) ? (p23.y + r4[ii].w) : maskvalL;

            float mx = fmaxf(fmaxf(x0, x1), fmaxf(x2, x3));
#pragma unroll
            for (int off = 8; off > 0; off >>= 1)   // xor<=8 stays in 16-lane half
                mx = fmaxf(mx, __shfl_xor_sync(0xffffffffu, mx, off));

            const float m_new = fmaxf(m4[ii], mx);
            const float e0 = exp2f(x0 - m_new);
            const float e1 = exp2f(x1 - m_new);
            const float e2 = exp2f(x2 - m_new);
            const float e3 = exp2f(x3 - m_new);

            float sm = (e0 + e1) + (e2 + e3);
#pragma unroll
            for (int off = 8; off > 0; off >>= 1)
                sm += __shfl_xor_sync(0xffffffffu, sm, off);

            const float alpha = exp2f(m4[ii] - m_new);
            l4[ii] = l4[ii] * alpha + sm;
            m4[ii] = m_new;

            // rescale this row's PV accumulator (same-thread ownership)
            const ull ap = pack2(alpha, alpha);
            accJ[ii][0] = fmul2(accJ[ii][0], ap);
            accJ[ii][1] = fmul2(accJ[ii][1], ap);

            // probs to smem (single touch)
            *(float4*)(s_s + (ty * 4 + ii) * 68 + tx * 4) = make_float4(e0, e1, e2, e3);
        }
        __syncthreads();   // probs visible; QK done CTA-wide

        // --- PV: thread = 4i x 2d, FFMA2 packed over (even j, odd j) ---
        const int ib = ty * 4;
        const int d0 = tx * 2;
#pragma unroll 4
        for (int j4 = 0; j4 < 64; j4 += 4) {
            const ulonglong2 v0 = *(const ulonglong2*)(v_s + (d0 + 0) * 68 + j4);
            const ulonglong2 v1 = *(const ulonglong2*)(v_s + (d0 + 1) * 68 + j4);
#pragma unroll
            for (int ii = 0; ii < 4; ii++) {
                const ulonglong2 pp = *(const ulonglong2*)(s_s + (ib + ii) * 68 + j4);
                ffma2(accJ[ii][0], pp.x, v0.x);
                ffma2(accJ[ii][0], pp.y, v0.y);
                ffma2(accJ[ii][1], pp.x, v1.x);
                ffma2(accJ[ii][1], pp.y, v1.y);
            }
        }

        if (hasn) {
            __syncthreads();   // all reads of k_s/v_s/s_s done
#pragma unroll
            for (int u = 0; u < 2; u++) {
                const int f4 = tid + u * 256;
                const int j  = f4 >> 3;
                const int dd = (f4 & 7) * 4;
                k_s[(dd + 0) * 68 + j] = kr[u].x;
                k_s[(dd + 1) * 68 + j] = kr[u].y;
                k_s[(dd + 2) * 68 + j] = kr[u].z;
                k_s[(dd + 3) * 68 + j] = kr[u].w;
                v_s[(dd + 0) * 68 + j] = vr[u].x;
                v_s[(dd + 1) * 68 + j] = vr[u].y;
                v_s[(dd + 2) * 68 + j] = vr[u].z;
                v_s[(dd + 3) * 68 + j] = vr[u].w;
            }
            __syncthreads();   // new tile visible
        }
    }

    // epilogue: l lives in-thread (replicated across the 16-lane j-group)
    const int ib = ty * 4;
    const int d0 = tx * 2;
#pragma unroll
    for (int ii = 0; ii < 4; ii++) {
        const float inv = 1.0f / l4[ii];
        const float2 o0 = unpack2(accJ[ii][0]);
        const float2 o1 = unpack2(accJ[ii][1]);
        float2 res;
        res.x = (o0.x + o0.y) * inv;
        res.y = (o1.x + o1.y) * inv;
        *(float2*)(out + ((size_t)(b * S_ + i0 + ib + ii)) * D_ + h * DH_ + d0) = res;
    }
}

// ---------------------------------------------------------------------------
extern "C" void kernel_launch(void* const* d_in, const int* in_sizes, int n_in,
                              void* d_out, int out_size)
{
    const float* x     = (const float*)d_in[0];
    const float* p     = (const float*)d_in[1];
    const int*   mask  = (const int*)  d_in[2];
    const float* Wqkv  = (const float*)d_in[3];
    const float* bqkv  = (const float*)d_in[4];
    const float* Wrqk  = (const float*)d_in[5];
    const float* brqk  = (const float*)d_in[6];
    float* out = (float*)d_out;

    (void)in_sizes; (void)n_in; (void)out_size;

    qkv_gemm_kernel<<<dim3(1536 / 128, 2048 / 128), 256>>>(x, Wqkv, bqkv);
    sums_kernel<<<(B_ * H_ * S_) / 256, 256>>>();
    radd_kernel<<<dim3(S_, B_), 256>>>(p, Wrqk, brqk);
    attn_kernel<<<dim3(S_ / 64, H_, B_), 256>>>(mask, out);
}